// round 2
// baseline (speedup 1.0000x reference)
#include <cuda_runtime.h>

#define NROWS 8192
#define DIM   2048
#define CEPS    1e-12f
#define CMARGIN 0.3f

// Scratch (allocation-free rule: __device__ globals)
__device__ float        g_xn[(size_t)NROWS * DIM];   // normalized rows, 64 MB
__device__ unsigned int g_minpos[NROWS];             // float bits (positive -> uint-ordered)
__device__ unsigned int g_maxneg[NROWS];
__device__ int          g_lbl[NROWS];

// ---------------------------------------------------------------------------
// Kernel 1: row L2-normalize + init per-row min/max + label copy
// ---------------------------------------------------------------------------
__global__ void __launch_bounds__(256) k_normalize(const float* __restrict__ x,
                                                   const int* __restrict__ tgt) {
    const int row = blockIdx.x;
    const float4* xr = (const float4*)(x + (size_t)row * DIM);
    float4 v0 = xr[threadIdx.x];
    float4 v1 = xr[threadIdx.x + 256];
    float ss = v0.x*v0.x + v0.y*v0.y + v0.z*v0.z + v0.w*v0.w
             + v1.x*v1.x + v1.y*v1.y + v1.z*v1.z + v1.w*v1.w;

    __shared__ float sred[8];
    #pragma unroll
    for (int o = 16; o; o >>= 1) ss += __shfl_xor_sync(0xffffffffu, ss, o);
    if ((threadIdx.x & 31) == 0) sred[threadIdx.x >> 5] = ss;
    __syncthreads();
    if (threadIdx.x == 0) {
        float t = 0.f;
        #pragma unroll
        for (int i = 0; i < 8; i++) t += sred[i];
        sred[0] = 1.0f / fmaxf(sqrtf(t), CEPS);
        g_lbl[row]    = tgt[row];          // targets arrive as int32
        g_minpos[row] = 0x7f800000u;       // +inf
        g_maxneg[row] = 0u;                // sims are > 0, so 0 == -inf here
    }
    __syncthreads();
    const float inv = sred[0];
    v0.x *= inv; v0.y *= inv; v0.z *= inv; v0.w *= inv;
    v1.x *= inv; v1.y *= inv; v1.z *= inv; v1.w *= inv;
    float4* o = (float4*)(g_xn + (size_t)row * DIM);
    o[threadIdx.x]       = v0;
    o[threadIdx.x + 256] = v1;
}

// ---------------------------------------------------------------------------
// Kernel 2: fused tiled sim-GEMM + masked min/max epilogue
// 128x128 tile, BK=16, 256 threads, 8x8 per thread, double-buffered smem.
// ---------------------------------------------------------------------------
#define BM 128
#define BN 128
#define BK 16

__global__ void __launch_bounds__(256, 2) k_sim() {
    __shared__ float As[2][BK][BM];
    __shared__ float Bs[2][BK][BN];
    __shared__ int   lr[BM], lc[BN];

    const int tid = threadIdx.x;
    const int tx  = tid & 15;
    const int ty  = tid >> 4;
    const int bi  = blockIdx.y * BM;
    const int bj  = blockIdx.x * BN;

    if (tid < BM) lr[tid] = g_lbl[bi + tid];
    else          lc[tid - BM] = g_lbl[bj + (tid - BM)];

    float acc[8][8];
    #pragma unroll
    for (int m = 0; m < 8; m++)
        #pragma unroll
        for (int n = 0; n < 8; n++) acc[m][n] = 0.f;

    float4 va[2], vb[2];

    auto loadG = [&](int k0) {
        #pragma unroll
        for (int it = 0; it < 2; it++) {
            const int idx = tid + it * 256;
            const int r = idx >> 2;
            const int c = (idx & 3) << 2;
            va[it] = *(const float4*)(g_xn + (size_t)(bi + r) * DIM + k0 + c);
            vb[it] = *(const float4*)(g_xn + (size_t)(bj + r) * DIM + k0 + c);
        }
    };
    auto storeS = [&](int b) {
        #pragma unroll
        for (int it = 0; it < 2; it++) {
            const int idx = tid + it * 256;
            const int r = idx >> 2;
            const int c = (idx & 3) << 2;
            As[b][c+0][r] = va[it].x; As[b][c+1][r] = va[it].y;
            As[b][c+2][r] = va[it].z; As[b][c+3][r] = va[it].w;
            Bs[b][c+0][r] = vb[it].x; Bs[b][c+1][r] = vb[it].y;
            Bs[b][c+2][r] = vb[it].z; Bs[b][c+3][r] = vb[it].w;
        }
    };

    loadG(0);
    storeS(0);
    __syncthreads();

    const int nk = DIM / BK;  // 128
    for (int t = 0; t < nk; t++) {
        const int b = t & 1;
        if (t + 1 < nk) loadG((t + 1) * BK);
        #pragma unroll
        for (int k = 0; k < BK; k++) {
            float4 a0 = *(const float4*)&As[b][k][ty * 8];
            float4 a1 = *(const float4*)&As[b][k][ty * 8 + 4];
            float4 b0 = *(const float4*)&Bs[b][k][tx * 8];
            float4 b1 = *(const float4*)&Bs[b][k][tx * 8 + 4];
            const float ra[8] = {a0.x,a0.y,a0.z,a0.w,a1.x,a1.y,a1.z,a1.w};
            const float rb[8] = {b0.x,b0.y,b0.z,b0.w,b1.x,b1.y,b1.z,b1.w};
            #pragma unroll
            for (int m = 0; m < 8; m++)
                #pragma unroll
                for (int n = 0; n < 8; n++)
                    acc[m][n] += ra[m] * rb[n];
        }
        if (t + 1 < nk) {
            storeS(b ^ 1);
            __syncthreads();
        }
    }

    // Epilogue: clamp, mask, per-thread min/max over this thread's 8 cols
    float pmin[8], pmax[8];
    #pragma unroll
    for (int m = 0; m < 8; m++) {
        pmin[m] = __uint_as_float(0x7f800000u);
        pmax[m] = 0.f;
        const int lbl = lr[ty * 8 + m];
        #pragma unroll
        for (int n = 0; n < 8; n++) {
            const float s = fmaxf(acc[m][n], CEPS);
            if (lbl == lc[tx * 8 + n]) pmin[m] = fminf(pmin[m], s);
            else                       pmax[m] = fmaxf(pmax[m], s);
        }
    }

    __syncthreads();  // everyone done with As/Bs -> reuse as reduce scratch
    float* redmin = (float*)As;   // [BM][17] padded
    float* redmax = (float*)Bs;
    #pragma unroll
    for (int m = 0; m < 8; m++) {
        redmin[(ty * 8 + m) * 17 + tx] = pmin[m];
        redmax[(ty * 8 + m) * 17 + tx] = pmax[m];
    }
    __syncthreads();

    if (tid < BM) {
        float mn = __uint_as_float(0x7f800000u);
        float mx = 0.f;
        #pragma unroll
        for (int i = 0; i < 16; i++) {
            mn = fminf(mn, redmin[tid * 17 + i]);
            mx = fmaxf(mx, redmax[tid * 17 + i]);
        }
        atomicMin(&g_minpos[bi + tid], __float_as_uint(mn));
        atomicMax(&g_maxneg[bi + tid], __float_as_uint(mx));
    }
}

// ---------------------------------------------------------------------------
// Kernel 3: final hinge-loss mean
// ---------------------------------------------------------------------------
__global__ void __launch_bounds__(256) k_loss(float* __restrict__ out) {
    float s = 0.f;
    for (int i = threadIdx.x; i < NROWS; i += 256) {
        const float ap = __uint_as_float(g_minpos[i]);
        const float an = __uint_as_float(g_maxneg[i]);
        s += fmaxf(an - ap + CMARGIN, 0.f);
    }
    __shared__ float sred[8];
    #pragma unroll
    for (int o = 16; o; o >>= 1) s += __shfl_xor_sync(0xffffffffu, s, o);
    if ((threadIdx.x & 31) == 0) sred[threadIdx.x >> 5] = s;
    __syncthreads();
    if (threadIdx.x == 0) {
        float t = 0.f;
        #pragma unroll
        for (int i = 0; i < 8; i++) t += sred[i];
        out[0] = t / (float)NROWS;
    }
}

// ---------------------------------------------------------------------------
extern "C" void kernel_launch(void* const* d_in, const int* in_sizes, int n_in,
                              void* d_out, int out_size) {
    const float* x   = (const float*)d_in[0];
    const int*   tgt = (const int*)d_in[1];
    float*       out = (float*)d_out;

    k_normalize<<<NROWS, 256>>>(x, tgt);
    dim3 grid(NROWS / BN, NROWS / BM);
    k_sim<<<grid, 256>>>();
    k_loss<<<1, 256>>>(out);
}

// round 4
// speedup vs baseline: 7.3981x; 7.3981x over previous
#include <cuda_runtime.h>
#include <cuda_bf16.h>
#include <cstdint>

#define NROWS 8192
#define DIM   2048
#define CEPS    1e-12f
#define CMARGIN 0.3f

// Scratch (__device__ globals: allocation-free rule)
__device__ __nv_bfloat16 g_bf[(size_t)NROWS * DIM];   // normalized rows, bf16, 32 MB
__device__ unsigned int  g_minpos[NROWS];             // positive floats as ordered uints
__device__ unsigned int  g_maxneg[NROWS];
__device__ int           g_lbl[NROWS];

// ---------------------------------------------------------------------------
// Kernel 1: row L2-normalize -> bf16, init per-row min/max, copy labels
// ---------------------------------------------------------------------------
__global__ void __launch_bounds__(256) k_normalize(const float* __restrict__ x,
                                                   const int* __restrict__ tgt) {
    const int row = blockIdx.x;
    const float4* xr = (const float4*)(x + (size_t)row * DIM);
    float4 v0 = xr[threadIdx.x];
    float4 v1 = xr[threadIdx.x + 256];
    float ss = v0.x*v0.x + v0.y*v0.y + v0.z*v0.z + v0.w*v0.w
             + v1.x*v1.x + v1.y*v1.y + v1.z*v1.z + v1.w*v1.w;

    __shared__ float sred[8];
    #pragma unroll
    for (int o = 16; o; o >>= 1) ss += __shfl_xor_sync(0xffffffffu, ss, o);
    if ((threadIdx.x & 31) == 0) sred[threadIdx.x >> 5] = ss;
    __syncthreads();
    if (threadIdx.x == 0) {
        float t = 0.f;
        #pragma unroll
        for (int i = 0; i < 8; i++) t += sred[i];
        sred[0] = 1.0f / fmaxf(sqrtf(t), CEPS);
        g_lbl[row]    = tgt[row];
        g_minpos[row] = 0x7f800000u;   // +inf
        g_maxneg[row] = 0u;            // sims > 0, so 0 stands in for -inf
    }
    __syncthreads();
    const float inv = sred[0];
    __nv_bfloat162* o = (__nv_bfloat162*)(g_bf + (size_t)row * DIM);
    o[threadIdx.x * 2 + 0]         = __nv_bfloat162(__float2bfloat16(v0.x * inv), __float2bfloat16(v0.y * inv));
    o[threadIdx.x * 2 + 1]         = __nv_bfloat162(__float2bfloat16(v0.z * inv), __float2bfloat16(v0.w * inv));
    o[(threadIdx.x + 256) * 2 + 0] = __nv_bfloat162(__float2bfloat16(v1.x * inv), __float2bfloat16(v1.y * inv));
    o[(threadIdx.x + 256) * 2 + 1] = __nv_bfloat162(__float2bfloat16(v1.z * inv), __float2bfloat16(v1.w * inv));
}

// ---------------------------------------------------------------------------
// Kernel 2: bf16 mma.sync sim-GEMM, 128x128 tile, BK=32, 2-stage cp.async,
// fused masked min/max epilogue. Baseline-PTX only (sm_100-safe).
// ---------------------------------------------------------------------------
#define BM 128
#define BN 128
#define BK 32
#define NCH (DIM / BK)            // 64
#define ROWB (BK * 2)             // 64 bytes per smem row
#define STAGE_B (BM * ROWB)       // 8192 bytes per stage

#define SW64(o) ((o) ^ (((o) >> 3) & 0x30))

__device__ __forceinline__ uint32_t smem_u32(const void* p) {
    uint32_t a;
    asm("{ .reg .u64 t; cvta.to.shared.u64 t, %1; cvt.u32.u64 %0, t; }" : "=r"(a) : "l"(p));
    return a;
}
__device__ __forceinline__ void cp16(uint32_t dst, const void* src) {
    asm volatile("cp.async.cg.shared.global [%0], [%1], 16;" :: "r"(dst), "l"(src) : "memory");
}
__device__ __forceinline__ void ldsm4(uint32_t (&r)[4], uint32_t addr) {
    asm volatile("ldmatrix.sync.aligned.m8n8.x4.shared.b16 {%0,%1,%2,%3}, [%4];"
                 : "=r"(r[0]), "=r"(r[1]), "=r"(r[2]), "=r"(r[3]) : "r"(addr));
}
__device__ __forceinline__ void hmma(float (&d)[4], const uint32_t (&a)[4],
                                     uint32_t b0, uint32_t b1) {
    asm volatile(
        "mma.sync.aligned.m16n8k16.row.col.f32.bf16.bf16.f32 "
        "{%0,%1,%2,%3}, {%4,%5,%6,%7}, {%8,%9}, {%0,%1,%2,%3};"
        : "+f"(d[0]), "+f"(d[1]), "+f"(d[2]), "+f"(d[3])
        : "r"(a[0]), "r"(a[1]), "r"(a[2]), "r"(a[3]), "r"(b0), "r"(b1));
}

__global__ void __launch_bounds__(256, 2) k_sim() {
    __shared__ __align__(1024) char sA[2][STAGE_B];
    __shared__ __align__(1024) char sB[2][STAGE_B];
    __shared__ int lr[BM], lc[BN];

    const int tid = threadIdx.x;
    const int wid = tid >> 5, lid = tid & 31;
    const int wr = wid >> 2;          // 0..1 -> m offset wr*64
    const int wc = wid & 3;           // 0..3 -> n offset wc*32
    const int bi = blockIdx.y * BM;
    const int bj = blockIdx.x * BN;

    if (tid < BM) lr[tid] = g_lbl[bi + tid];
    else          lc[tid - BM] = g_lbl[bj + (tid - BM)];

    const uint32_t sAb = smem_u32(sA), sBb = smem_u32(sB);

    // cp.async issue: each thread copies 2x16B for A and 2x16B for B per chunk
    auto issue = [&](int t, int stg) {
        const int k0 = t * BK;
        #pragma unroll
        for (int i = 0; i < 2; i++) {
            const int idx = tid + i * 256;         // 0..511
            const int r = idx >> 2, c = idx & 3;   // row, 16B-chunk
            const uint32_t so = SW64((uint32_t)(r * ROWB + c * 16));
            cp16(sAb + stg * STAGE_B + so, g_bf + (size_t)(bi + r) * DIM + k0 + c * 8);
            cp16(sBb + stg * STAGE_B + so, g_bf + (size_t)(bj + r) * DIM + k0 + c * 8);
        }
        asm volatile("cp.async.commit_group;" ::: "memory");
    };

    float acc[4][4][4];
    #pragma unroll
    for (int m = 0; m < 4; m++)
        #pragma unroll
        for (int n = 0; n < 4; n++)
            #pragma unroll
            for (int e = 0; e < 4; e++) acc[m][n][e] = 0.f;

    // ldmatrix per-lane address components (x4: lane -> matrix lid>>3, row lid&7)
    const int q = lid >> 3, qrow = lid & 7;

    issue(0, 0);
    for (int t = 0; t < NCH; t++) {
        const int stg = t & 1;
        if (t + 1 < NCH) issue(t + 1, stg ^ 1);
        if (t + 1 < NCH) asm volatile("cp.async.wait_group 1;" ::: "memory");
        else             asm volatile("cp.async.wait_group 0;" ::: "memory");
        __syncthreads();

        #pragma unroll
        for (int ks = 0; ks < 2; ks++) {           // two k16 steps per chunk
            uint32_t afr[4][4];                    // [mtile][4 regs]
            #pragma unroll
            for (int mi = 0; mi < 4; mi++) {
                // x4 matrices: (m0..7,k0-7),(m8..15,k0-7),(m0..7,k8-15),(m8..15,k8-15)
                const int row = wr * 64 + mi * 16 + (q & 1) * 8 + qrow;
                const uint32_t off = (uint32_t)(row * ROWB + ks * 32 + (q >> 1) * 16);
                ldsm4(afr[mi], sAb + stg * STAGE_B + SW64(off));
            }
            uint32_t bfr[2][4];                    // [npair][4 regs]
            #pragma unroll
            for (int p = 0; p < 2; p++) {
                const int nrow = wc * 32 + p * 16 + (q & 1) * 8 + qrow;
                const uint32_t off = (uint32_t)(nrow * ROWB + ks * 32 + (q >> 1) * 16);
                ldsm4(bfr[p], sBb + stg * STAGE_B + SW64(off));
            }
            #pragma unroll
            for (int mi = 0; mi < 4; mi++)
                #pragma unroll
                for (int p = 0; p < 2; p++) {
                    hmma(acc[mi][p * 2 + 0], afr[mi], bfr[p][0], bfr[p][2]);
                    hmma(acc[mi][p * 2 + 1], afr[mi], bfr[p][1], bfr[p][3]);
                }
        }
        __syncthreads();
    }

    // -----------------------------------------------------------------------
    // Epilogue: clamp, mask by label, per-row min/max -> smem reduce -> atomics
    // Fragment C: c0,c1 -> row g, cols 2t,2t+1 ; c2,c3 -> row g+8
    // -----------------------------------------------------------------------
    const int g = lid >> 2, tq = lid & 3;
    float rmn[8], rmx[8];                          // 4 mtiles x 2 rows
    #pragma unroll
    for (int mi = 0; mi < 4; mi++) {
        #pragma unroll
        for (int h = 0; h < 2; h++) {
            float mn = __uint_as_float(0x7f800000u), mx = 0.f;
            const int row = wr * 64 + mi * 16 + h * 8 + g;
            const int myl = lr[row];
            #pragma unroll
            for (int ni = 0; ni < 4; ni++) {
                #pragma unroll
                for (int e = 0; e < 2; e++) {
                    const float s = fmaxf(acc[mi][ni][h * 2 + e], CEPS);
                    const int col = wc * 32 + ni * 8 + tq * 2 + e;
                    if (lc[col] == myl) mn = fminf(mn, s);
                    else                mx = fmaxf(mx, s);
                }
            }
            rmn[mi * 2 + h] = mn; rmx[mi * 2 + h] = mx;
        }
    }

    float* redmin = (float*)sA;                    // [128][17]
    float* redmax = redmin + BM * 17;              // fits in sA (8704B each < 16384)
    #pragma unroll
    for (int mi = 0; mi < 4; mi++)
        #pragma unroll
        for (int h = 0; h < 2; h++) {
            const int row = wr * 64 + mi * 16 + h * 8 + g;
            redmin[row * 17 + wc * 4 + tq] = rmn[mi * 2 + h];
            redmax[row * 17 + wc * 4 + tq] = rmx[mi * 2 + h];
        }
    __syncthreads();

    if (tid < BM) {
        float mn = __uint_as_float(0x7f800000u), mx = 0.f;
        #pragma unroll
        for (int i = 0; i < 16; i++) {
            mn = fminf(mn, redmin[tid * 17 + i]);
            mx = fmaxf(mx, redmax[tid * 17 + i]);
        }
        atomicMin(&g_minpos[bi + tid], __float_as_uint(mn));
        atomicMax(&g_maxneg[bi + tid], __float_as_uint(mx));
    }
}

// ---------------------------------------------------------------------------
// Kernel 3: final hinge-loss mean
// ---------------------------------------------------------------------------
__global__ void __launch_bounds__(256) k_loss(float* __restrict__ out) {
    float s = 0.f;
    for (int i = threadIdx.x; i < NROWS; i += 256) {
        const float ap = __uint_as_float(g_minpos[i]);
        const float an = __uint_as_float(g_maxneg[i]);
        s += fmaxf(an - ap + CMARGIN, 0.f);
    }
    __shared__ float sred[8];
    #pragma unroll
    for (int o = 16; o; o >>= 1) s += __shfl_xor_sync(0xffffffffu, s, o);
    if ((threadIdx.x & 31) == 0) sred[threadIdx.x >> 5] = s;
    __syncthreads();
    if (threadIdx.x == 0) {
        float t = 0.f;
        #pragma unroll
        for (int i = 0; i < 8; i++) t += sred[i];
        out[0] = t / (float)NROWS;
    }
}

// ---------------------------------------------------------------------------
extern "C" void kernel_launch(void* const* d_in, const int* in_sizes, int n_in,
                              void* d_out, int out_size) {
    const float* x   = (const float*)d_in[0];
    const int*   tgt = (const int*)d_in[1];
    float*       out = (float*)d_out;

    k_normalize<<<NROWS, 256>>>(x, tgt);
    dim3 grid(NROWS / BN, NROWS / BM);   // (64, 64)
    k_sim<<<grid, 256>>>();
    k_loss<<<1, 256>>>(out);
}

// round 5
// speedup vs baseline: 13.2889x; 1.7963x over previous
#include <cuda_runtime.h>
#include <cuda_bf16.h>
#include <cstdint>

#define NROWS 8192
#define DIM   2048
#define CEPS    1e-12f
#define CMARGIN 0.3f
#define NT   (NROWS / 128)        // 64 tiles per dim
#define NPAIR (NT * (NT + 1) / 2) // 2080 upper-triangle tiles

// Scratch (__device__ globals: allocation-free rule)
__device__ __nv_bfloat16 g_bf[(size_t)NROWS * DIM];   // normalized rows, bf16, 32 MB
__device__ unsigned int  g_minpos[NROWS];             // positive floats as ordered uints
__device__ unsigned int  g_maxneg[NROWS];
__device__ int           g_lbl[NROWS];

// ---------------------------------------------------------------------------
// Kernel 1: row L2-normalize -> bf16, init per-row min/max, copy labels
// ---------------------------------------------------------------------------
__global__ void __launch_bounds__(256) k_normalize(const float* __restrict__ x,
                                                   const int* __restrict__ tgt) {
    const int row = blockIdx.x;
    const float4* xr = (const float4*)(x + (size_t)row * DIM);
    float4 v0 = xr[threadIdx.x];
    float4 v1 = xr[threadIdx.x + 256];
    float ss = v0.x*v0.x + v0.y*v0.y + v0.z*v0.z + v0.w*v0.w
             + v1.x*v1.x + v1.y*v1.y + v1.z*v1.z + v1.w*v1.w;

    __shared__ float sred[8];
    #pragma unroll
    for (int o = 16; o; o >>= 1) ss += __shfl_xor_sync(0xffffffffu, ss, o);
    if ((threadIdx.x & 31) == 0) sred[threadIdx.x >> 5] = ss;
    __syncthreads();
    if (threadIdx.x == 0) {
        float t = 0.f;
        #pragma unroll
        for (int i = 0; i < 8; i++) t += sred[i];
        sred[0] = 1.0f / fmaxf(sqrtf(t), CEPS);
        g_lbl[row]    = tgt[row];
        g_minpos[row] = 0x7f800000u;   // +inf
        g_maxneg[row] = 0u;            // sims > 0, so 0 stands in for -inf
    }
    __syncthreads();
    const float inv = sred[0];
    __nv_bfloat162* o = (__nv_bfloat162*)(g_bf + (size_t)row * DIM);
    o[threadIdx.x * 2 + 0]         = __nv_bfloat162(__float2bfloat16(v0.x * inv), __float2bfloat16(v0.y * inv));
    o[threadIdx.x * 2 + 1]         = __nv_bfloat162(__float2bfloat16(v0.z * inv), __float2bfloat16(v0.w * inv));
    o[(threadIdx.x + 256) * 2 + 0] = __nv_bfloat162(__float2bfloat16(v1.x * inv), __float2bfloat16(v1.y * inv));
    o[(threadIdx.x + 256) * 2 + 1] = __nv_bfloat162(__float2bfloat16(v1.z * inv), __float2bfloat16(v1.w * inv));
}

// ---------------------------------------------------------------------------
// Kernel 2: bf16 mma.sync sim-GEMM on upper-triangle tiles only.
// 128x128 tile, BK=32, 2-stage cp.async. Epilogue updates BOTH row stats
// (rows bi) and column stats (rows bj) — min/max idempotence makes the
// diagonal-tile double-count harmless.
// ---------------------------------------------------------------------------
#define BM 128
#define BN 128
#define BK 32
#define NCH (DIM / BK)            // 64
#define ROWB (BK * 2)             // 64 bytes per smem row
#define STAGE_B (BM * ROWB)       // 8192 bytes per stage

#define SW64(o) ((o) ^ (((o) >> 3) & 0x30))

__device__ __forceinline__ uint32_t smem_u32(const void* p) {
    uint32_t a;
    asm("{ .reg .u64 t; cvta.to.shared.u64 t, %1; cvt.u32.u64 %0, t; }" : "=r"(a) : "l"(p));
    return a;
}
__device__ __forceinline__ void cp16(uint32_t dst, const void* src) {
    asm volatile("cp.async.cg.shared.global [%0], [%1], 16;" :: "r"(dst), "l"(src) : "memory");
}
__device__ __forceinline__ void ldsm4(uint32_t (&r)[4], uint32_t addr) {
    asm volatile("ldmatrix.sync.aligned.m8n8.x4.shared.b16 {%0,%1,%2,%3}, [%4];"
                 : "=r"(r[0]), "=r"(r[1]), "=r"(r[2]), "=r"(r[3]) : "r"(addr));
}
__device__ __forceinline__ void hmma(float (&d)[4], const uint32_t (&a)[4],
                                     uint32_t b0, uint32_t b1) {
    asm volatile(
        "mma.sync.aligned.m16n8k16.row.col.f32.bf16.bf16.f32 "
        "{%0,%1,%2,%3}, {%4,%5,%6,%7}, {%8,%9}, {%0,%1,%2,%3};"
        : "+f"(d[0]), "+f"(d[1]), "+f"(d[2]), "+f"(d[3])
        : "r"(a[0]), "r"(a[1]), "r"(a[2]), "r"(a[3]), "r"(b0), "r"(b1));
}

__global__ void __launch_bounds__(256, 2) k_sim() {
    __shared__ __align__(1024) char sA[2][STAGE_B];
    __shared__ __align__(1024) char sB[2][STAGE_B];
    __shared__ int lr[BM], lc[BN];

    const int tid = threadIdx.x;
    const int wid = tid >> 5, lid = tid & 31;
    const int wr = wid >> 2;          // 0..1 -> m offset wr*64
    const int wc = wid & 3;           // 0..3 -> n offset wc*32
    // --- triangular decode: p -> (i, j), i <= j -------------------------------
    const int p = blockIdx.x;
    int ti = (int)(64.5f - sqrtf(64.5f * 64.5f - 2.0f * (float)p));
    while (NT * ti - ti * (ti - 1) / 2 > p) ti--;
    while (NT * (ti + 1) - (ti + 1) * ti / 2 <= p) ti++;
    const int tj = ti + (p - (NT * ti - ti * (ti - 1) / 2));
    const int bi = ti * BM;
    const int bj = tj * BN;

    if (tid < BM) lr[tid] = g_lbl[bi + tid];
    else          lc[tid - BM] = g_lbl[bj + (tid - BM)];

    const uint32_t sAb = smem_u32(sA), sBb = smem_u32(sB);

    auto issue = [&](int t, int stg) {
        const int k0 = t * BK;
        #pragma unroll
        for (int i = 0; i < 2; i++) {
            const int idx = tid + i * 256;         // 0..511
            const int r = idx >> 2, c = idx & 3;   // row, 16B-chunk
            const uint32_t so = SW64((uint32_t)(r * ROWB + c * 16));
            cp16(sAb + stg * STAGE_B + so, g_bf + (size_t)(bi + r) * DIM + k0 + c * 8);
            cp16(sBb + stg * STAGE_B + so, g_bf + (size_t)(bj + r) * DIM + k0 + c * 8);
        }
        asm volatile("cp.async.commit_group;" ::: "memory");
    };

    float acc[4][4][4];
    #pragma unroll
    for (int m = 0; m < 4; m++)
        #pragma unroll
        for (int n = 0; n < 4; n++)
            #pragma unroll
            for (int e = 0; e < 4; e++) acc[m][n][e] = 0.f;

    const int q = lid >> 3, qrow = lid & 7;

    issue(0, 0);
    for (int t = 0; t < NCH; t++) {
        const int stg = t & 1;
        if (t + 1 < NCH) issue(t + 1, stg ^ 1);
        if (t + 1 < NCH) asm volatile("cp.async.wait_group 1;" ::: "memory");
        else             asm volatile("cp.async.wait_group 0;" ::: "memory");
        __syncthreads();

        #pragma unroll
        for (int ks = 0; ks < 2; ks++) {
            uint32_t afr[4][4];
            #pragma unroll
            for (int mi = 0; mi < 4; mi++) {
                const int row = wr * 64 + mi * 16 + (q & 1) * 8 + qrow;
                const uint32_t off = (uint32_t)(row * ROWB + ks * 32 + (q >> 1) * 16);
                ldsm4(afr[mi], sAb + stg * STAGE_B + SW64(off));
            }
            uint32_t bfr[2][4];
            #pragma unroll
            for (int pp = 0; pp < 2; pp++) {
                const int nrow = wc * 32 + pp * 16 + (q & 1) * 8 + qrow;
                const uint32_t off = (uint32_t)(nrow * ROWB + ks * 32 + (q >> 1) * 16);
                ldsm4(bfr[pp], sBb + stg * STAGE_B + SW64(off));
            }
            #pragma unroll
            for (int mi = 0; mi < 4; mi++)
                #pragma unroll
                for (int pp = 0; pp < 2; pp++) {
                    hmma(acc[mi][pp * 2 + 0], afr[mi], bfr[pp][0], bfr[pp][2]);
                    hmma(acc[mi][pp * 2 + 1], afr[mi], bfr[pp][1], bfr[pp][3]);
                }
        }
        __syncthreads();
    }

    // -----------------------------------------------------------------------
    // Epilogue. Fragment C: (c0,c1)->row g cols 2tq,2tq+1 ; (c2,c3)->row g+8.
    // Pass 1: row stats -> rows bi.  Pass 2: col stats -> rows bj.
    // -----------------------------------------------------------------------
    const int g = lid >> 2, tq = lid & 3;
    float rmn[8], rmx[8];              // per (mi,h): stats over this thread's 8 cols
    float cmn[8], cmx[8];              // per (ni,e): stats over this thread's 8 rows
    #pragma unroll
    for (int i = 0; i < 8; i++) {
        cmn[i] = __uint_as_float(0x7f800000u);
        cmx[i] = 0.f;
    }
    #pragma unroll
    for (int mi = 0; mi < 4; mi++) {
        #pragma unroll
        for (int h = 0; h < 2; h++) {
            float mn = __uint_as_float(0x7f800000u), mx = 0.f;
            const int row = wr * 64 + mi * 16 + h * 8 + g;
            const int myl = lr[row];
            #pragma unroll
            for (int ni = 0; ni < 4; ni++) {
                #pragma unroll
                for (int e = 0; e < 2; e++) {
                    const float s = fmaxf(acc[mi][ni][h * 2 + e], CEPS);
                    const int col = wc * 32 + ni * 8 + tq * 2 + e;
                    const int ce = ni * 2 + e;
                    if (lc[col] == myl) { mn = fminf(mn, s); cmn[ce] = fminf(cmn[ce], s); }
                    else                { mx = fmaxf(mx, s); cmx[ce] = fmaxf(cmx[ce], s); }
                }
            }
            rmn[mi * 2 + h] = mn; rmx[mi * 2 + h] = mx;
        }
    }

    // Pass 1: row reduce (rows bi).  [128][17] x2 fits in sA (16KB).
    float* redmin = (float*)sA;
    float* redmax = redmin + BM * 17;
    #pragma unroll
    for (int mi = 0; mi < 4; mi++)
        #pragma unroll
        for (int h = 0; h < 2; h++) {
            const int row = wr * 64 + mi * 16 + h * 8 + g;
            redmin[row * 17 + wc * 4 + tq] = rmn[mi * 2 + h];
            redmax[row * 17 + wc * 4 + tq] = rmx[mi * 2 + h];
        }
    __syncthreads();
    if (tid < BM) {
        float mn = __uint_as_float(0x7f800000u), mx = 0.f;
        #pragma unroll
        for (int i = 0; i < 16; i++) {
            mn = fminf(mn, redmin[tid * 17 + i]);
            mx = fmaxf(mx, redmax[tid * 17 + i]);
        }
        atomicMin(&g_minpos[bi + tid], __float_as_uint(mn));
        atomicMax(&g_maxneg[bi + tid], __float_as_uint(mx));
    }
    __syncthreads();

    // Pass 2: col reduce (rows bj).  slot = wr*8 + g (16 slots per col).
    #pragma unroll
    for (int ni = 0; ni < 4; ni++)
        #pragma unroll
        for (int e = 0; e < 2; e++) {
            const int col = wc * 32 + ni * 8 + tq * 2 + e;
            redmin[col * 17 + wr * 8 + g] = cmn[ni * 2 + e];
            redmax[col * 17 + wr * 8 + g] = cmx[ni * 2 + e];
        }
    __syncthreads();
    if (tid < BN) {
        float mn = __uint_as_float(0x7f800000u), mx = 0.f;
        #pragma unroll
        for (int i = 0; i < 16; i++) {
            mn = fminf(mn, redmin[tid * 17 + i]);
            mx = fmaxf(mx, redmax[tid * 17 + i]);
        }
        atomicMin(&g_minpos[bj + tid], __float_as_uint(mn));
        atomicMax(&g_maxneg[bj + tid], __float_as_uint(mx));
    }
}

// ---------------------------------------------------------------------------
// Kernel 3: final hinge-loss mean
// ---------------------------------------------------------------------------
__global__ void __launch_bounds__(256) k_loss(float* __restrict__ out) {
    float s = 0.f;
    for (int i = threadIdx.x; i < NROWS; i += 256) {
        const float ap = __uint_as_float(g_minpos[i]);
        const float an = __uint_as_float(g_maxneg[i]);
        s += fmaxf(an - ap + CMARGIN, 0.f);
    }
    __shared__ float sred[8];
    #pragma unroll
    for (int o = 16; o; o >>= 1) s += __shfl_xor_sync(0xffffffffu, s, o);
    if ((threadIdx.x & 31) == 0) sred[threadIdx.x >> 5] = s;
    __syncthreads();
    if (threadIdx.x == 0) {
        float t = 0.f;
        #pragma unroll
        for (int i = 0; i < 8; i++) t += sred[i];
        out[0] = t / (float)NROWS;
    }
}

// ---------------------------------------------------------------------------
extern "C" void kernel_launch(void* const* d_in, const int* in_sizes, int n_in,
                              void* d_out, int out_size) {
    const float* x   = (const float*)d_in[0];
    const int*   tgt = (const int*)d_in[1];
    float*       out = (float*)d_out;

    k_normalize<<<NROWS, 256>>>(x, tgt);
    k_sim<<<NPAIR, 256>>>();
    k_loss<<<1, 256>>>(out);
}